// round 6
// baseline (speedup 1.0000x reference)
#include <cuda_runtime.h>
#include <stdint.h>
#include <math.h>

#define BATCH 8
#define NANCH 100000
#define NGT   64
#define NTOK  256
#define TOPK  27
#define NEG_INF -100000000.0f

#define BINS   64
#define NBIN   (BINS * BINS)        // 4096 bins per batch
#define INVBIN 0.0625f              // 1/16 px
#define U64MAX 0xFFFFFFFFFFFFFFFFULL

// ---------------- device scratch ----------------
__device__ float2             g_centers [BATCH * NANCH];
__device__ int                g_bin     [BATCH * NANCH];    // precomputed bin id per anchor
__device__ int                g_hist    [BATCH * NBIN];
__device__ int                g_binstart[BATCH * NBIN];     // prefix: starts -> (after scatter) inclusive ends
__device__ int                g_order   [BATCH * NANCH];    // counting-sorted anchor indices
__device__ unsigned long long g_match   [BATCH * NANCH];    // packed (iou<<32 | 63-g), 0 = unmatched

// ---------------- kernel 0: zero hist ----------------
__global__ void zero_kernel() {
    int i = blockIdx.x * blockDim.x + threadIdx.x;
    if (i < BATCH * NBIN) g_hist[i] = 0;
}

// ---------------- kernel 1: centers + bin id + histogram + clear match ----------------
__global__ void prep_kernel(const float* __restrict__ anchors) {
    int i = blockIdx.x * blockDim.x + threadIdx.x;
    if (i >= BATCH * NANCH) return;
    float4 a = ((const float4*)anchors)[i];
    float cx = (a.x + a.z) * 0.5f;
    float cy = (a.y + a.w) * 0.5f;
    g_centers[i] = make_float2(cx, cy);
    g_match[i] = 0ULL;
    int b  = i / NANCH;
    int bx = min(BINS - 1, max(0, (int)(cx * INVBIN)));
    int by = min(BINS - 1, max(0, (int)(cy * INVBIN)));
    int bin = by * BINS + bx;
    g_bin[i] = bin;
    atomicAdd(&g_hist[b * NBIN + bin], 1);
}

// ---------------- kernel 2: per-batch exclusive prefix over 4096 bins ----------------
__global__ __launch_bounds__(1024) void prefix_kernel() {
    const int b = blockIdx.x, t = threadIdx.x;
    int c[4];
    int base = b * NBIN + t * 4;
#pragma unroll
    for (int j = 0; j < 4; j++) c[j] = g_hist[base + j];
    int sum = c[0] + c[1] + c[2] + c[3];

    __shared__ int sc[1024];
    sc[t] = sum;
    __syncthreads();
    for (int off = 1; off < 1024; off <<= 1) {
        int v = (t >= off) ? sc[t - off] : 0;
        __syncthreads();
        sc[t] += v;
        __syncthreads();
    }
    int run = sc[t] - sum;                      // exclusive prefix
#pragma unroll
    for (int j = 0; j < 4; j++) { g_binstart[base + j] = run; run += c[j]; }
}

// ---------------- kernel 3: counting-sort scatter (short chain, cursor = binstart) ----------------
__global__ void binscatter_kernel() {
    int i = blockIdx.x * blockDim.x + threadIdx.x;
    if (i >= BATCH * NANCH) return;
    int bin = g_bin[i];                          // coalesced 4B load
    int b = i / NANCH, n = i % NANCH;
    int dst = atomicAdd(&g_binstart[b * NBIN + bin], 1);   // starts become ends in place
    g_order[b * NANCH + dst] = n;
}

// insert p into sorted (ascending) reg array best[0..26]; caller guarantees p < best[26]
#define INSERT27(best, p)                                               \
    {                                                                   \
        _Pragma("unroll")                                               \
        for (int k = TOPK - 1; k >= 0; --k) {                           \
            if (k == 0 || (p) >= best[k - 1]) { best[k] = (p); break; } \
            best[k] = best[k - 1];                                      \
        }                                                               \
    }

// ---------------- kernel 4: per-gt windowed exact top-27 + IoU + scatter ----------------
// g_binstart now holds INCLUSIVE ENDS: start(bin) = (bin==0) ? 0 : ends[bin-1]
__global__ __launch_bounds__(32) void gt_kernel(const float* __restrict__ anchors,
                                                const float* __restrict__ gts) {
    const int bg   = blockIdx.x;
    const int b    = bg / NGT;
    const int lane = threadIdx.x;

    const float4 gt = ((const float4*)gts)[bg];
    const float gcx = (gt.x + gt.z) * 0.5f;
    const float gcy = (gt.y + gt.w) * 0.5f;

    const int*    __restrict__ ord  = g_order   + b * NANCH;
    const float2* __restrict__ cen  = g_centers + b * NANCH;
    const int*    __restrict__ ends = g_binstart + b * NBIN;

    __shared__ unsigned long long skey[TOPK];
    __shared__ float siou[TOPK];
    __shared__ int   sing[TOPK];
    __shared__ float sthr;

    float W = 16.0f;
    for (;;) {
        int bx0 = max(0, (int)((gcx - W) * INVBIN));
        int bx1 = min(BINS - 1, (int)((gcx + W) * INVBIN));
        int by0 = max(0, (int)((gcy - W) * INVBIN));
        int by1 = min(BINS - 1, (int)((gcy + W) * INVBIN));

        int total = 0;
        for (int by = by0; by <= by1; by++) {
            int bin0 = by * BINS + bx0;
            int s = (bin0 == 0) ? 0 : ends[bin0 - 1];
            total += ends[by * BINS + bx1] - s;
        }

        // per-lane sorted top-27 over window row segments
        unsigned long long best[TOPK];
#pragma unroll
        for (int k = 0; k < TOPK; k++) best[k] = U64MAX;

        for (int by = by0; by <= by1; by++) {
            int bin0 = by * BINS + bx0;
            int s = (bin0 == 0) ? 0 : ends[bin0 - 1];
            int e = ends[by * BINS + bx1];
            for (int i = s + lane; i < e; i += 32) {
                int n = ord[i];
                float2 c = cen[n];
                float dx = c.x - gcx, dy = c.y - gcy;
                float d2 = dx * dx + dy * dy;
                // integer-domain filter: positive-float bits are order-isomorphic,
                // and the 0xFFFFFFFF sentinel (NaN as float!) compares correctly here
                if (__float_as_uint(d2) <= (unsigned)(best[TOPK - 1] >> 32)) {
                    unsigned long long pk =
                        (((unsigned long long)__float_as_uint(d2)) << 32) |
                        (unsigned)n;
                    if (pk < best[TOPK - 1]) INSERT27(best, pk);
                }
            }
        }

        // warp merge: 27 rounds of head-min
        int head = 0;
        for (int r = 0; r < TOPK; r++) {
            unsigned long long c = (head < TOPK) ? best[head] : U64MAX;
            unsigned long long m = c;
#pragma unroll
            for (int s = 16; s > 0; s >>= 1) {
                unsigned long long o = __shfl_xor_sync(0xFFFFFFFFu, m, s);
                if (o < m) m = o;
            }
            if (lane == 0) skey[r] = m;
            if (c == m) head++;
        }
        __syncwarp();

        bool full_canvas = (bx0 == 0 && bx1 == BINS - 1 && by0 == 0 && by1 == BINS - 1);
        float d27sq = __uint_as_float((unsigned)(skey[TOPK - 1] >> 32));
        if ((total >= TOPK && d27sq < W * W * 0.999f) || full_canvas) break;
        W *= 2.0f;
    }

    // IoU + center-inside for the 27 winners
    if (lane < TOPK) {
        int n = (int)(skey[lane] & 0xFFFFFFFFu);
        float4 a = ((const float4*)anchors)[b * NANCH + n];
        float area_a = (a.z - a.x) * (a.w - a.y);
        float area_g = (gt.z - gt.x) * (gt.w - gt.y);
        float lx = fmaxf(a.x, gt.x), ly = fmaxf(a.y, gt.y);
        float rx = fminf(a.z, gt.z), ry = fminf(a.w, gt.w);
        float w = fmaxf(rx - lx, 0.0f), h = fmaxf(ry - ly, 0.0f);
        float inter = w * h;
        float uni = area_a + area_g - inter;
        siou[lane] = __fdiv_rn(inter, uni);

        float acx = (a.x + a.z) * 0.5f, acy = (a.y + a.w) * 0.5f;
        float l  = acx - gt.x;
        float tp = acy - gt.y;
        float rr = gt.z - acx;
        float bb = gt.w - acy;
        float mn = fminf(fminf(l, tp), fminf(rr, bb));
        sing[lane] = (mn > 0.01f) ? 1 : 0;
    }
    __syncwarp();

    if (lane == 0) {
        double s = 0.0, ss = 0.0;
        for (int k = 0; k < TOPK; k++) {
            double v = (double)siou[k];
            s += v; ss += v * v;
        }
        double mean = s / TOPK;
        double var  = (ss - s * s / TOPK) / (TOPK - 1);   // ddof=1 (unbiased)
        if (var < 0.0) var = 0.0;
        sthr = (float)(mean + sqrt(var));
    }
    __syncwarp();

    // fused scatter: argmax over gts via packed atomicMax (positives have iou > 0)
    if (lane < TOPK) {
        float iou = siou[lane];
        if (iou >= sthr && sing[lane]) {
            int n = (int)(skey[lane] & 0xFFFFFFFFu);
            int g = bg % NGT;
            unsigned long long p =
                (((unsigned long long)__float_as_uint(iou)) << 32) |
                (unsigned)(NGT - 1 - g);
            atomicMax(&g_match[b * NANCH + n], p);
        }
    }
}

// ---------------- kernel 5: fused outputs — scalars + matched_gts + token_labels ----------------
__global__ __launch_bounds__(256) void output_kernel(const float* __restrict__ gts,
                                                     const float* __restrict__ tokens,
                                                     float* __restrict__ out) {
    int warp = (blockIdx.x * blockDim.x + threadIdx.x) >> 5;
    int lane = threadIdx.x & 31;
    if (warp >= BATCH * NANCH) return;
    int b = warp / NANCH;
    unsigned long long m = g_match[warp];   // same address across warp -> broadcast

    int g; float val;
    if (m) {
        g   = NGT - 1 - (int)(m & 0xFFFFFFFFu);
        val = __uint_as_float((unsigned)(m >> 32));
    } else {
        g = 0; val = NEG_INF;               // argmax of all -INF row is 0
    }

    if (lane == 0) {
        out[warp]                 = val;                       // values
        out[BATCH * NANCH + warp] = (float)g;                  // indices
        float4 gtb = ((const float4*)gts)[b * NGT + g];
        ((float4*)(out + 2 * (size_t)BATCH * NANCH))[warp] = gtb;  // matched_gts
    }

    float4* dst = (float4*)(out + (size_t)6 * BATCH * NANCH) + (size_t)warp * (NTOK / 4);
    if (m) {
        const float4* src = (const float4*)(tokens + ((size_t)b * NGT + g) * NTOK);
        __stcs(dst + lane,      __ldg(src + lane));
        __stcs(dst + lane + 32, __ldg(src + lane + 32));
    } else {
        float4 z = make_float4(0.f, 0.f, 0.f, 0.f);
        __stcs(dst + lane, z);
        float4 z2 = z;
        if (lane == 31) z2.w = 1.0f;        // one-hot at token index 255
        __stcs(dst + lane + 32, z2);
    }
}

// ---------------- launch ----------------
extern "C" void kernel_launch(void* const* d_in, const int* in_sizes, int n_in,
                              void* d_out, int out_size) {
    const float* anchors = (const float*)d_in[0];   // [8,100000,4]
    const float* gts     = (const float*)d_in[1];   // [8,64,4]
    const float* tokens  = (const float*)d_in[2];   // [8,64,256]
    float* out = (float*)d_out;

    zero_kernel<<<(BATCH * NBIN + 255) / 256, 256>>>();
    prep_kernel<<<(BATCH * NANCH + 255) / 256, 256>>>(anchors);
    prefix_kernel<<<BATCH, 1024>>>();
    binscatter_kernel<<<(BATCH * NANCH + 255) / 256, 256>>>();
    gt_kernel<<<BATCH * NGT, 32>>>(anchors, gts);
    output_kernel<<<(BATCH * NANCH * 32 + 255) / 256, 256>>>(gts, tokens, out);
}